// round 7
// baseline (speedup 1.0000x reference)
#include <cuda_runtime.h>
#include <cstdint>

// Problem constants
#define NB   8
#define TPD  2048
#define ED   4096
#define TD   16384
#define VD   17
#define OUTROWS 131072
#define KS   8             // K-splits
#define KCHUNK 512         // ED/KS
#define KT   8             // K per pipeline stage
#define NSTAGE (KCHUNK/KT) // 64
#define MROWS 512          // rows per k3 block
#define RMAX 16384         // hard upper bound on per-batch masked count

typedef unsigned long long ull;

// Scratch (device globals)
__device__ float g_WeffQ[8 * 1024 * 32];      // [s0][q][32] quad-interleaved Weff
__device__ float g_beff[8];
__device__ int   g_bucket[64 * 2048];         // [(n*8+s0)][slot] = (r<<16)|tp
__device__ int   g_bcount[64];
__device__ int   g_count8[NB];                // 8 * per-batch masked count
__device__ float g_part[(size_t)KS * NB * RMAX * 8];  // [ks][n][r][s]

// ---------------------------------------------------------------------------
__device__ __forceinline__ void ffma2(ull& d, ull a, ull b) {
    asm("fma.rn.f32x2 %0, %1, %2, %0;" : "+l"(d) : "l"(a), "l"(b));
}
__device__ __forceinline__ void ldgsts16(void* dst, const void* src) {
    unsigned saddr = (unsigned)__cvta_generic_to_shared(dst);
    asm volatile("cp.async.cg.shared.global [%0], [%1], 16;\n" :: "r"(saddr), "l"(src));
}
__device__ __forceinline__ void cp_commit() {
    asm volatile("cp.async.commit_group;\n" ::: "memory");
}
template <int N>
__device__ __forceinline__ void cp_wait() {
    asm volatile("cp.async.wait_group %0;\n" :: "n"(N) : "memory");
}

// ---------------------------------------------------------------------------
// K01 fused, 1024 threads/block:
//   blocks [0,8): per-batch argmax + bucketed compaction (coalesced int4,
//                 4 passes of 4096 elems, carried scan bases)
//   blocks [8,264): WeffQ for 16 e-values each (+beff at block 8)
// ---------------------------------------------------------------------------
__global__ __launch_bounds__(1024) void k01(const float* __restrict__ W1,
                                            const float* __restrict__ W2,
                                            const float* __restrict__ b1,
                                            const float* __restrict__ b2,
                                            const int* __restrict__ value,
                                            const int* __restrict__ depth) {
    int bid = blockIdx.x;
    int tid = threadIdx.x;

    if (bid >= 8) {
        // ---- Weff: 16 e-values per block ----
        __shared__ __align__(16) float w2s[512];
        __shared__ __align__(16) float w1r[16][512];
        int e0 = (bid - 8) * 16;
        if (tid < 128) ((float4*)w2s)[tid] = ((const float4*)W2)[tid];
        ((float4*)&w1r[0][0])[tid]        = ((const float4*)(W1 + (size_t)e0 * 512))[tid];
        ((float4*)&w1r[0][0])[tid + 1024] = ((const float4*)(W1 + (size_t)e0 * 512))[tid + 1024];
        __syncthreads();
        int sub = tid >> 6;       // which e (0..15)
        int t64 = tid & 63;
        int s0 = t64 >> 3, s = t64 & 7;
        int e = e0 + sub;
        float acc = 0.f;
#pragma unroll
        for (int c = 0; c < 64; c++) acc += w1r[sub][c * 8 + s0] * w2s[c * 8 + s];
        int q = e >> 2, p = (e >> 1) & 1, h = e & 1;
        g_WeffQ[(s0 * 1024 + q) * 32 + p * 16 + s * 2 + h] = acc;
        if (bid == 8 && tid < 8) {
            float a = 0.f;
#pragma unroll
            for (int c = 0; c < 64; c++) a += b1[c] * w2s[c * 8 + tid];
            g_beff[tid] = a + b2[0];
        }
    } else {
        // ---- prep: batch n, 1024 threads, coalesced int4, 4 passes ----
        int n = bid;
        const int* dep = depth + n * TD;
        const int* val = value + n * TD;
        __shared__ int s_idx;
        __shared__ int wsum[32];
        __shared__ ull wtA[32], wtB[32];
        __shared__ int wbase[32 * 8];
        __shared__ int sb_r;
        __shared__ int sb_s0[8];
        __shared__ int pass_tot;
        __shared__ int pass_tot_s0[8];

        int lane = tid & 31, wid = tid >> 5;  // 32 warps

        int maxv = dep[TD - 1];
        if (tid == 0) { s_idx = TD; sb_r = 0; }
        if (tid < 8) sb_s0[tid] = 0;
        __syncthreads();
        // argmax: first index where dep hits max (dep sorted ascending)
        for (int t0 = tid * 4; t0 < TD; t0 += 4096) {
            int4 d = *(const int4*)(dep + t0);
            int prev = (t0 == 0) ? (maxv - 1) : dep[t0 - 1];
            if (d.x == maxv && prev < maxv) atomicMin(&s_idx, t0);
            if (d.y == maxv && d.x < maxv) atomicMin(&s_idx, t0 + 1);
            if (d.z == maxv && d.y < maxv) atomicMin(&s_idx, t0 + 2);
            if (d.w == maxv && d.z < maxv) atomicMin(&s_idx, t0 + 3);
        }
        __syncthreads();
        int idx = s_idx;
        int bb = n * 8;

        for (int pass = 0; pass < 4; pass++) {
            int t0 = pass * 4096 + tid * 4;
            int4 vv = *(const int4*)(val + t0);
            int vj[4] = {vv.x, vv.y, vv.z, vv.w};
            unsigned mb = 0;
            int cnt = 0;
            ull cA = 0, cB = 0;  // per-s0 counts, 16-bit fields (s0 0-3 / 4-7)
#pragma unroll
            for (int j = 0; j < 4; j++) {
                int t = t0 + j;
                bool m = (t < idx) && (vj[j] == 2);
                mb |= ((unsigned)m) << j;
                cnt += (int)m;
                if (m) {
                    int f = t & 7;
                    if (f < 4) cA += 1ull << (f * 16);
                    else       cB += 1ull << ((f - 4) * 16);
                }
            }
            // warp inclusive scans
            int v = cnt;
            ull ciA = cA, ciB = cB;
#pragma unroll
            for (int o = 1; o < 32; o <<= 1) {
                int u  = __shfl_up_sync(0xffffffffu, v, o);
                ull uA = __shfl_up_sync(0xffffffffu, ciA, o);
                ull uB = __shfl_up_sync(0xffffffffu, ciB, o);
                if (lane >= o) { v += u; ciA += uA; ciB += uB; }
            }
            if (lane == 31) { wsum[wid] = v; wtA[wid] = ciA; wtB[wid] = ciB; }
            __syncthreads();
            if (wid == 0) {
                // exclusive scan of 32 warp totals (rank)
                int w = wsum[lane];
                int wi = w;
#pragma unroll
                for (int o = 1; o < 32; o <<= 1) {
                    int u = __shfl_up_sync(0xffffffffu, wi, o);
                    if (lane >= o) wi += u;
                }
                wsum[lane] = wi - w;
                if (lane == 31) pass_tot = wi;
            } else if (wid == 1 && lane < 8) {
                int s0 = lane;
                int run = 0;
#pragma unroll
                for (int w = 0; w < 32; w++) {
                    int c = (s0 < 4) ? (int)((wtA[w] >> (s0 * 16)) & 0xFFFF)
                                     : (int)((wtB[w] >> ((s0 - 4) * 16)) & 0xFFFF);
                    wbase[w * 8 + s0] = run;
                    run += c;
                }
                pass_tot_s0[s0] = run;
            }
            __syncthreads();
            int r = sb_r + wsum[wid] + (v - cnt);
            ull exA = ciA - cA, exB = ciB - cB;
#pragma unroll
            for (int j = 0; j < 4; j++) {
                if ((mb >> j) & 1u) {
                    int t = t0 + j;
                    int s0 = t & 7;
                    int ex = (s0 < 4) ? (int)((exA >> (s0 * 16)) & 0xFFFF)
                                      : (int)((exB >> ((s0 - 4) * 16)) & 0xFFFF);
                    int slot = sb_s0[s0] + wbase[wid * 8 + s0] + ex;
                    g_bucket[(bb + s0) * 2048 + slot] = (r << 16) | (t >> 3);
                    if (s0 < 4) exA += 1ull << (s0 * 16);
                    else        exB += 1ull << ((s0 - 4) * 16);
                    r++;
                }
            }
            __syncthreads();
            if (tid == 0) sb_r += pass_tot;
            if (tid < 8) sb_s0[tid] += pass_tot_s0[tid];
            __syncthreads();
        }
        if (tid < 8) g_bcount[bb + tid] = sb_s0[tid];
        if (tid == 0) g_count8[n] = 8 * sb_r;
    }
}

// ---------------------------------------------------------------------------
// K3: bucketed GEMM. 128 threads/block, 512 rows/block, thread owns 4 rows
// (tid, +128, +256, +384) x all 8 s. X staged via cp.async (q-major mapping,
// XSTRIDE=12 -> conflict-free STS and LDS), W warp-broadcast, f32x2 FMA.
// K split by ks into 512-float chunks; 64 double-buffered stages of KT=8.
// blockIdx.x = rb*64 + ks*8 + s0 (s0 fastest for L2 reuse across buckets).
// ---------------------------------------------------------------------------
#define XSTRIDE 12

__global__ __launch_bounds__(128) void k3_heavy(const float* __restrict__ x) {
    int bx = blockIdx.x;
    int s0 = bx & 7, ks = (bx >> 3) & 7, rb = bx >> 6;
    int n = blockIdx.y;
    int bucket = n * 8 + s0;
    int bcnt = g_bcount[bucket];
    int row0 = rb * MROWS;
    if (row0 >= bcnt) return;
    int tid = threadIdx.x;

    __shared__ __align__(16) float Xs[2][MROWS][XSTRIDE];  // 48KB
    __shared__ __align__(16) float Wsm[2][2][32];          // 512B
    __shared__ int stp_s[MROWS];
    __shared__ int sr_s[MROWS];

    // prologue: row metadata (coalesced)
#pragma unroll
    for (int i = 0; i < 4; i++) {
        int li = tid + 128 * i;
        int gr = row0 + li;
        if (gr < bcnt) {
            int p = g_bucket[bucket * 2048 + gr];
            sr_s[li] = p >> 16;
            stp_s[li] = p & 0xFFFF;
        } else {
            sr_s[li] = -1;
            stp_s[li] = 0;
        }
    }
    __syncthreads();

    const float* xb = x + (size_t)n * TPD * ED + ks * KCHUNK;
    const float* wb = g_WeffQ + (size_t)(s0 * 1024 + ks * 128) * 32;

    // q-major loader: gidx = i*128+tid; row = gidx & 511; q = gidx >> 9.
    // Lanes walk consecutive rows (same q): smem banks 12*r mod 32 are
    // distinct across any 8 consecutive rows -> conflict-free STS.
    auto load_stage = [&](int st, int b) {
        int kbase = st * KT;
#pragma unroll
        for (int i = 0; i < 8; i++) {
            int gidx = i * 128 + tid;
            int row = gidx & 511, q = gidx >> 9;
            ldgsts16(&Xs[b][row][q * 4],
                     xb + (size_t)stp_s[row] * ED + kbase + q * 4);
        }
        if (tid < 16) {
            ldgsts16(&Wsm[b][0][0] + tid * 4, wb + st * 64 + tid * 4);
        }
        cp_commit();
    };

    load_stage(0, 0);

    ull acc[4][8];
#pragma unroll
    for (int i = 0; i < 4; i++)
#pragma unroll
        for (int s = 0; s < 8; s++) acc[i][s] = 0ull;

    for (int st = 0; st < NSTAGE; st++) {
        int b = st & 1;
        if (st + 1 < NSTAGE) {
            load_stage(st + 1, b ^ 1);
            cp_wait<1>();
        } else {
            cp_wait<0>();
        }
        __syncthreads();

#pragma unroll
        for (int q = 0; q < 2; q++) {
            ulonglong2 xq[4];
#pragma unroll
            for (int i = 0; i < 4; i++)
                xq[i] = *(const ulonglong2*)&Xs[b][tid + 128 * i][q * 4];
            const ull* wq = (const ull*)&Wsm[b][q][0];
#pragma unroll
            for (int sp = 0; sp < 4; sp++) {
                ulonglong2 w0 = *(const ulonglong2*)(wq + sp * 2);      // p=0
                ulonglong2 w1 = *(const ulonglong2*)(wq + 8 + sp * 2);  // p=1
#pragma unroll
                for (int i = 0; i < 4; i++) {
                    ffma2(acc[i][2 * sp],     xq[i].x, w0.x);
                    ffma2(acc[i][2 * sp],     xq[i].y, w1.x);
                    ffma2(acc[i][2 * sp + 1], xq[i].x, w0.y);
                    ffma2(acc[i][2 * sp + 1], xq[i].y, w1.y);
                }
            }
        }
        __syncthreads();
    }

    // store partials
#pragma unroll
    for (int i = 0; i < 4; i++) {
        int li = tid + 128 * i;
        int rr = sr_s[li];
        if (rr < 0) continue;
        float y[8];
#pragma unroll
        for (int s = 0; s < 8; s++) {
            float2 f = *(float2*)&acc[i][s];
            y[s] = f.x + f.y;
        }
        float* dst = g_part + ((size_t)(ks * NB + n) * RMAX + rr) * 8;
        *(float4*)(dst)     = make_float4(y[0], y[1], y[2], y[3]);
        *(float4*)(dst + 4) = make_float4(y[4], y[5], y[6], y[7]);
    }
}

// ---------------------------------------------------------------------------
// K4: fused epilogue + default fill. Strip of 256 output rows per block.
// ---------------------------------------------------------------------------
__global__ __launch_bounds__(256) void k4_epi(const float* __restrict__ W3,
                                              const float* __restrict__ b2,
                                              float* __restrict__ out) {
    int n = blockIdx.y;
    int j0 = blockIdx.x * 256;
    int tid = threadIdx.x;
    __shared__ float y2s[256];
    __shared__ float w3s[VD];
    __shared__ float beffs[8];
    if (tid < VD) w3s[tid] = W3[tid];
    if (tid < 8) beffs[tid] = g_beff[tid];
    __syncthreads();

    int count8 = g_count8[n];
    int j = j0 + tid;
    float acc;
    if (j < count8) {
        acc = beffs[j & 7];
#pragma unroll
        for (int ksi = 0; ksi < KS; ksi++)
            acc += g_part[(size_t)(ksi * NB + n) * (RMAX * 8) + j];
    } else {
        acc = b2[0];
    }
    y2s[tid] = acc;
    __syncthreads();

    float* ob = out + ((size_t)n * OUTROWS + j0) * VD;
    const int NF4 = 256 * VD / 4;  // 1088
    for (int f = tid; f < NF4; f += 256) {
        float4 o;
#pragma unroll
        for (int c = 0; c < 4; c++) {
            int idx = f * 4 + c;
            int jj = idx / VD;
            int vv = idx - jj * VD;
            ((float*)&o)[c] = y2s[jj] * w3s[vv];
        }
        *(float4*)(ob + f * 4) = o;
    }
}

// ---------------------------------------------------------------------------
extern "C" void kernel_launch(void* const* d_in, const int* in_sizes, int n_in,
                              void* d_out, int out_size) {
    const float* x     = (const float*)d_in[0];
    const int*   value = (const int*)d_in[1];   // jax x64-off: int32
    const int*   depth = (const int*)d_in[2];
    // d_in[3] = pos, unused
    const float* W1    = (const float*)d_in[4];
    const float* b1    = (const float*)d_in[5];
    const float* W2    = (const float*)d_in[6];
    const float* b2    = (const float*)d_in[7];
    const float* W3    = (const float*)d_in[8];
    float* out = (float*)d_out;

    k01<<<264, 1024>>>(W1, W2, b1, b2, value, depth);
    k3_heavy<<<dim3(256, NB), 128>>>(x);
    k4_epi<<<dim3(OUTROWS / 256, NB), 256>>>(W3, b2, out);
}

// round 8
// speedup vs baseline: 1.4866x; 1.4866x over previous
#include <cuda_runtime.h>
#include <cstdint>

// Problem constants
#define NB   8
#define TPD  2048
#define ED   4096
#define TD   16384
#define VD   17
#define OUTROWS 131072
#define KS   8             // K-splits
#define KCHUNK 512         // ED/KS
#define KT   16            // K per pipeline stage
#define NSTAGE (KCHUNK/KT) // 32
#define MROWS 256          // rows per k3 block
#define RMAX 16384         // hard upper bound on per-batch masked count

typedef unsigned long long ull;

// Scratch (device globals)
__device__ float g_WeffQ[8 * 1024 * 32];      // [s0][q][32] quad-interleaved Weff
__device__ float g_beff[8];
__device__ int   g_bucket[64 * 2048];         // [(n*8+s0)][slot] = (r<<16)|tp
__device__ int   g_bcount[64];
__device__ int   g_count8[NB];                // 8 * per-batch masked count
__device__ float g_part[(size_t)KS * NB * RMAX * 8];  // [ks][n][r][s]

// ---------------------------------------------------------------------------
__device__ __forceinline__ void ffma2(ull& d, ull a, ull b) {
    asm("fma.rn.f32x2 %0, %1, %2, %0;" : "+l"(d) : "l"(a), "l"(b));
}
__device__ __forceinline__ void ldgsts16(void* dst, const void* src) {
    unsigned saddr = (unsigned)__cvta_generic_to_shared(dst);
    asm volatile("cp.async.cg.shared.global [%0], [%1], 16;\n" :: "r"(saddr), "l"(src));
}
__device__ __forceinline__ void cp_commit() {
    asm volatile("cp.async.commit_group;\n" ::: "memory");
}
template <int N>
__device__ __forceinline__ void cp_wait() {
    asm volatile("cp.async.wait_group %0;\n" :: "n"(N) : "memory");
}

// ---------------------------------------------------------------------------
// K01 fused, 1024 threads/block:
//   blocks [0,8): per-batch argmax + bucketed compaction (coalesced int4,
//                 4 passes of 4096 elems, carried scan bases)
//   blocks [8,264): WeffQ for 16 e-values each (+beff at block 8)
// ---------------------------------------------------------------------------
__global__ __launch_bounds__(1024) void k01(const float* __restrict__ W1,
                                            const float* __restrict__ W2,
                                            const float* __restrict__ b1,
                                            const float* __restrict__ b2,
                                            const int* __restrict__ value,
                                            const int* __restrict__ depth) {
    int bid = blockIdx.x;
    int tid = threadIdx.x;

    if (bid >= 8) {
        // ---- Weff: 16 e-values per block ----
        __shared__ __align__(16) float w2s[512];
        __shared__ __align__(16) float w1r[16][512];
        int e0 = (bid - 8) * 16;
        if (tid < 128) ((float4*)w2s)[tid] = ((const float4*)W2)[tid];
        ((float4*)&w1r[0][0])[tid]        = ((const float4*)(W1 + (size_t)e0 * 512))[tid];
        ((float4*)&w1r[0][0])[tid + 1024] = ((const float4*)(W1 + (size_t)e0 * 512))[tid + 1024];
        __syncthreads();
        int sub = tid >> 6;       // which e (0..15)
        int t64 = tid & 63;
        int s0 = t64 >> 3, s = t64 & 7;
        int e = e0 + sub;
        float acc = 0.f;
#pragma unroll
        for (int c = 0; c < 64; c++) acc += w1r[sub][c * 8 + s0] * w2s[c * 8 + s];
        int q = e >> 2, p = (e >> 1) & 1, h = e & 1;
        g_WeffQ[(s0 * 1024 + q) * 32 + p * 16 + s * 2 + h] = acc;
        if (bid == 8 && tid < 8) {
            float a = 0.f;
#pragma unroll
            for (int c = 0; c < 64; c++) a += b1[c] * w2s[c * 8 + tid];
            g_beff[tid] = a + b2[0];
        }
    } else {
        // ---- prep: batch n, 1024 threads, coalesced int4, 4 passes ----
        int n = bid;
        const int* dep = depth + n * TD;
        const int* val = value + n * TD;
        __shared__ int s_idx;
        __shared__ int wsum[32];
        __shared__ ull wtA[32], wtB[32];
        __shared__ int wbase[32 * 8];
        __shared__ int sb_r;
        __shared__ int sb_s0[8];
        __shared__ int pass_tot;
        __shared__ int pass_tot_s0[8];

        int lane = tid & 31, wid = tid >> 5;  // 32 warps

        int maxv = dep[TD - 1];
        if (tid == 0) { s_idx = TD; sb_r = 0; }
        if (tid < 8) sb_s0[tid] = 0;
        __syncthreads();
        // argmax: first index where dep hits max (dep sorted ascending)
        for (int t0 = tid * 4; t0 < TD; t0 += 4096) {
            int4 d = *(const int4*)(dep + t0);
            int prev = (t0 == 0) ? (maxv - 1) : dep[t0 - 1];
            if (d.x == maxv && prev < maxv) atomicMin(&s_idx, t0);
            if (d.y == maxv && d.x < maxv) atomicMin(&s_idx, t0 + 1);
            if (d.z == maxv && d.y < maxv) atomicMin(&s_idx, t0 + 2);
            if (d.w == maxv && d.z < maxv) atomicMin(&s_idx, t0 + 3);
        }
        __syncthreads();
        int idx = s_idx;
        int bb = n * 8;

        for (int pass = 0; pass < 4; pass++) {
            int t0 = pass * 4096 + tid * 4;
            int4 vv = *(const int4*)(val + t0);
            int vj[4] = {vv.x, vv.y, vv.z, vv.w};
            unsigned mb = 0;
            int cnt = 0;
            ull cA = 0, cB = 0;  // per-s0 counts, 16-bit fields (s0 0-3 / 4-7)
#pragma unroll
            for (int j = 0; j < 4; j++) {
                int t = t0 + j;
                bool m = (t < idx) && (vj[j] == 2);
                mb |= ((unsigned)m) << j;
                cnt += (int)m;
                if (m) {
                    int f = t & 7;
                    if (f < 4) cA += 1ull << (f * 16);
                    else       cB += 1ull << ((f - 4) * 16);
                }
            }
            // warp inclusive scans
            int v = cnt;
            ull ciA = cA, ciB = cB;
#pragma unroll
            for (int o = 1; o < 32; o <<= 1) {
                int u  = __shfl_up_sync(0xffffffffu, v, o);
                ull uA = __shfl_up_sync(0xffffffffu, ciA, o);
                ull uB = __shfl_up_sync(0xffffffffu, ciB, o);
                if (lane >= o) { v += u; ciA += uA; ciB += uB; }
            }
            if (lane == 31) { wsum[wid] = v; wtA[wid] = ciA; wtB[wid] = ciB; }
            __syncthreads();
            if (wid == 0) {
                // exclusive scan of 32 warp totals (rank)
                int w = wsum[lane];
                int wi = w;
#pragma unroll
                for (int o = 1; o < 32; o <<= 1) {
                    int u = __shfl_up_sync(0xffffffffu, wi, o);
                    if (lane >= o) wi += u;
                }
                wsum[lane] = wi - w;
                if (lane == 31) pass_tot = wi;
            } else if (wid == 1 && lane < 8) {
                int s0 = lane;
                int run = 0;
#pragma unroll
                for (int w = 0; w < 32; w++) {
                    int c = (s0 < 4) ? (int)((wtA[w] >> (s0 * 16)) & 0xFFFF)
                                     : (int)((wtB[w] >> ((s0 - 4) * 16)) & 0xFFFF);
                    wbase[w * 8 + s0] = run;
                    run += c;
                }
                pass_tot_s0[s0] = run;
            }
            __syncthreads();
            int r = sb_r + wsum[wid] + (v - cnt);
            ull exA = ciA - cA, exB = ciB - cB;
#pragma unroll
            for (int j = 0; j < 4; j++) {
                if ((mb >> j) & 1u) {
                    int t = t0 + j;
                    int s0 = t & 7;
                    int ex = (s0 < 4) ? (int)((exA >> (s0 * 16)) & 0xFFFF)
                                      : (int)((exB >> ((s0 - 4) * 16)) & 0xFFFF);
                    int slot = sb_s0[s0] + wbase[wid * 8 + s0] + ex;
                    g_bucket[(bb + s0) * 2048 + slot] = (r << 16) | (t >> 3);
                    if (s0 < 4) exA += 1ull << (s0 * 16);
                    else        exB += 1ull << ((s0 - 4) * 16);
                    r++;
                }
            }
            __syncthreads();
            if (tid == 0) sb_r += pass_tot;
            if (tid < 8) sb_s0[tid] += pass_tot_s0[tid];
            __syncthreads();
        }
        if (tid < 8) g_bcount[bb + tid] = sb_s0[tid];
        if (tid == 0) g_count8[n] = 8 * sb_r;
    }
}

// ---------------------------------------------------------------------------
// K3 (R6-proven): bucketed GEMM. 128 threads/block, 256 rows/block, thread
// owns 2 rows (tid, tid+128) x all 8 s. X staged via cp.async into smem with
// 20-float row stride (conflict-free LDS; STS 4-lanes-per-row = 64B
// contiguous global per lane-quad), W warp-broadcast, f32x2 FMA.
// K split by ks into 512-float chunks; 32 double-buffered stages of KT=16.
// blockIdx.x = rb*64 + ks*8 + s0 (s0,ks fastest for L2 reuse across buckets).
// ---------------------------------------------------------------------------
#define XSTRIDE 20

__global__ __launch_bounds__(128) void k3_heavy(const float* __restrict__ x) {
    int bx = blockIdx.x;
    int s0 = bx & 7, ks = (bx >> 3) & 7, rb = bx >> 6;
    int n = blockIdx.y;
    int bucket = n * 8 + s0;
    int bcnt = g_bcount[bucket];
    int row0 = rb * MROWS;
    if (row0 >= bcnt) return;
    int tid = threadIdx.x;

    __shared__ __align__(16) float Xs[2][MROWS][XSTRIDE];  // 40KB
    __shared__ __align__(16) float Wsm[2][4][32];          // 1KB
    __shared__ int stp_s[MROWS];
    __shared__ int sr_s[MROWS];

    // prologue: row metadata (coalesced)
#pragma unroll
    for (int i = 0; i < 2; i++) {
        int li = tid + 128 * i;
        int gr = row0 + li;
        if (gr < bcnt) {
            int p = g_bucket[bucket * 2048 + gr];
            sr_s[li] = p >> 16;
            stp_s[li] = p & 0xFFFF;
        } else {
            sr_s[li] = -1;
            stp_s[li] = 0;
        }
    }
    __syncthreads();

    const float* xb = x + (size_t)n * TPD * ED + ks * KCHUNK;
    const float* wb = g_WeffQ + (size_t)(s0 * 1024 + ks * 128) * 32;

    // loader mapping: gidx = i*128+tid; row = gidx>>2, q = gidx&3
    // (4 lanes cover one row's 4 quads -> 64B contiguous global)
    auto load_stage = [&](int st, int b) {
        int kbase = st * KT;
#pragma unroll
        for (int i = 0; i < 8; i++) {
            int gidx = i * 128 + tid;
            int row = gidx >> 2, q = gidx & 3;
            ldgsts16(&Xs[b][row][q * 4],
                     xb + (size_t)stp_s[row] * ED + kbase + q * 4);
        }
        if (tid < 32) {
            ldgsts16(&Wsm[b][0][tid * 4], wb + st * 128 + tid * 4);
        }
        cp_commit();
    };

    load_stage(0, 0);

    ull acc[2][8];
#pragma unroll
    for (int i = 0; i < 2; i++)
#pragma unroll
        for (int s = 0; s < 8; s++) acc[i][s] = 0ull;

    for (int st = 0; st < NSTAGE; st++) {
        int b = st & 1;
        if (st + 1 < NSTAGE) {
            load_stage(st + 1, b ^ 1);
            cp_wait<1>();
        } else {
            cp_wait<0>();
        }
        __syncthreads();

#pragma unroll
        for (int q = 0; q < 4; q++) {
            ulonglong2 xq[2];
#pragma unroll
            for (int i = 0; i < 2; i++)
                xq[i] = *(const ulonglong2*)&Xs[b][tid + 128 * i][q * 4];
            const ull* wq = (const ull*)&Wsm[b][q][0];
#pragma unroll
            for (int sp = 0; sp < 4; sp++) {
                ulonglong2 w0 = *(const ulonglong2*)(wq + sp * 2);      // p=0
                ulonglong2 w1 = *(const ulonglong2*)(wq + 8 + sp * 2);  // p=1
#pragma unroll
                for (int i = 0; i < 2; i++) {
                    ffma2(acc[i][2 * sp],     xq[i].x, w0.x);
                    ffma2(acc[i][2 * sp],     xq[i].y, w1.x);
                    ffma2(acc[i][2 * sp + 1], xq[i].x, w0.y);
                    ffma2(acc[i][2 * sp + 1], xq[i].y, w1.y);
                }
            }
        }
        __syncthreads();
    }

    // store partials
#pragma unroll
    for (int i = 0; i < 2; i++) {
        int li = tid + 128 * i;
        int rr = sr_s[li];
        if (rr < 0) continue;
        float y[8];
#pragma unroll
        for (int s = 0; s < 8; s++) {
            float2 f = *(float2*)&acc[i][s];
            y[s] = f.x + f.y;
        }
        float* dst = g_part + ((size_t)(ks * NB + n) * RMAX + rr) * 8;
        *(float4*)(dst)     = make_float4(y[0], y[1], y[2], y[3]);
        *(float4*)(dst + 4) = make_float4(y[4], y[5], y[6], y[7]);
    }
}

// ---------------------------------------------------------------------------
// K4: fused epilogue + default fill. Strip of 256 output rows per block.
// ---------------------------------------------------------------------------
__global__ __launch_bounds__(256) void k4_epi(const float* __restrict__ W3,
                                              const float* __restrict__ b2,
                                              float* __restrict__ out) {
    int n = blockIdx.y;
    int j0 = blockIdx.x * 256;
    int tid = threadIdx.x;
    __shared__ float y2s[256];
    __shared__ float w3s[VD];
    __shared__ float beffs[8];
    if (tid < VD) w3s[tid] = W3[tid];
    if (tid < 8) beffs[tid] = g_beff[tid];
    __syncthreads();

    int count8 = g_count8[n];
    int j = j0 + tid;
    float acc;
    if (j < count8) {
        acc = beffs[j & 7];
#pragma unroll
        for (int ksi = 0; ksi < KS; ksi++)
            acc += g_part[(size_t)(ksi * NB + n) * (RMAX * 8) + j];
    } else {
        acc = b2[0];
    }
    y2s[tid] = acc;
    __syncthreads();

    float* ob = out + ((size_t)n * OUTROWS + j0) * VD;
    const int NF4 = 256 * VD / 4;  // 1088
    for (int f = tid; f < NF4; f += 256) {
        float4 o;
#pragma unroll
        for (int c = 0; c < 4; c++) {
            int idx = f * 4 + c;
            int jj = idx / VD;
            int vv = idx - jj * VD;
            ((float*)&o)[c] = y2s[jj] * w3s[vv];
        }
        *(float4*)(ob + f * 4) = o;
    }
}

// ---------------------------------------------------------------------------
extern "C" void kernel_launch(void* const* d_in, const int* in_sizes, int n_in,
                              void* d_out, int out_size) {
    const float* x     = (const float*)d_in[0];
    const int*   value = (const int*)d_in[1];   // jax x64-off: int32
    const int*   depth = (const int*)d_in[2];
    // d_in[3] = pos, unused
    const float* W1    = (const float*)d_in[4];
    const float* b1    = (const float*)d_in[5];
    const float* W2    = (const float*)d_in[6];
    const float* b2    = (const float*)d_in[7];
    const float* W3    = (const float*)d_in[8];
    float* out = (float*)d_out;

    k01<<<264, 1024>>>(W1, W2, b1, b2, value, depth);
    k3_heavy<<<dim3(512, NB), 128>>>(x);
    k4_epi<<<dim3(OUTROWS / 256, NB), 256>>>(W3, b2, out);
}